// round 1
// baseline (speedup 1.0000x reference)
#include <cuda_runtime.h>

#define NSUB 64
#define NPTS 65536
#define WID  64

// Scratch: u_s(x_n) per subdomain per point. 64*65536*4 = 16 MB, static device array
// (no allocation — allowed). Every slot is written each call -> deterministic, no zeroing.
__device__ float g_u[NSUB * NPTS];

// ---------------------------------------------------------------------------
// Fast, accurate-enough tanh: tanh(x) = 1 - 2/(exp(2x)+1)
// ex2.approx rel err ~2^-22, rcp.approx ~2^-23 -> abs err ~1e-6. 2 MUFU ops.
// Saturates correctly: x->+inf: ex2->inf, rcp->0, result 1; x->-inf: ex2->0, result -1.
// ---------------------------------------------------------------------------
__device__ __forceinline__ float tanh_fast(float x) {
    float e;
    asm("ex2.approx.f32 %0, %1;" : "=f"(e) : "f"(x * 2.8853900817779268f)); // 2*log2(e)
    float r;
    asm("rcp.approx.f32 %0, %1;" : "=f"(r) : "f"(e + 1.0f));
    return fmaf(-2.0f, r, 1.0f);
}

// ---------------------------------------------------------------------------
// Packed f32x2 helpers (Blackwell FFMA2 — 2x fp32 FMA throughput)
// ---------------------------------------------------------------------------
__device__ __forceinline__ unsigned long long pack2(float lo, float hi) {
    unsigned long long p;
    asm("mov.b64 %0, {%1, %2};" : "=l"(p) : "f"(lo), "f"(hi));
    return p;
}
__device__ __forceinline__ void unpack2(unsigned long long p, float& lo, float& hi) {
    asm("mov.b64 {%0, %1}, %2;" : "=f"(lo), "=f"(hi) : "l"(p));
}
__device__ __forceinline__ unsigned long long fma2(unsigned long long a,
                                                   unsigned long long b,
                                                   unsigned long long c) {
    unsigned long long d;
    asm("fma.rn.f32x2 %0, %1, %2, %3;" : "=l"(d) : "l"(a), "l"(b), "l"(c));
    return d;
}

// ---------------------------------------------------------------------------
// One 64x64 hidden layer: h <- tanh(W @ h + b).
// Wt is the TRANSPOSED weight in smem: Wt[w*64 + v] = W[v][w], 16B-aligned.
// So an LDS.128 (ulonglong2) at row w gives {W[v0][w],W[v1][w]} | {W[v2][w],W[v3][w]}
// as ready-made f32x2 pairs -> zero packing cost on the weight side.
// Only h[w] needs one mov.b64 pack per w (ALU pipe, overlaps FMA pipe).
// ---------------------------------------------------------------------------
__device__ __forceinline__ void layer64(const float* __restrict__ Wt,
                                        const float* __restrict__ b,
                                        float h[WID]) {
    unsigned long long acc[32];
#pragma unroll
    for (int j = 0; j < 32; j++) acc[j] = pack2(b[2 * j], b[2 * j + 1]);
#pragma unroll
    for (int w = 0; w < 64; w++) {
        unsigned long long hp = pack2(h[w], h[w]);
        const ulonglong2* row = (const ulonglong2*)(Wt + w * 64);
#pragma unroll
        for (int j = 0; j < 16; j++) {
            ulonglong2 q = row[j];                 // LDS.128, broadcast (conflict-free)
            acc[2 * j]     = fma2(q.x, hp, acc[2 * j]);
            acc[2 * j + 1] = fma2(q.y, hp, acc[2 * j + 1]);
        }
    }
#pragma unroll
    for (int j = 0; j < 32; j++) {
        float lo, hi;
        unpack2(acc[j], lo, hi);
        h[2 * j]     = tanh_fast(lo);
        h[2 * j + 1] = tanh_fast(hi);
    }
}

// ---------------------------------------------------------------------------
// Kernel 1: per (subdomain s, 256-point tile), evaluate the tiny MLP.
// grid = (N/256, S), block = 256 threads, 1 point/thread.
// ---------------------------------------------------------------------------
__global__ __launch_bounds__(256, 1)
void fbpinn_mlp_kernel(const float* __restrict__ X,
                       const float* __restrict__ W0g, const float* __restrict__ B0g,
                       const float* __restrict__ W1g, const float* __restrict__ B1g,
                       const float* __restrict__ W2g, const float* __restrict__ B2g,
                       const float* __restrict__ W3g, const float* __restrict__ B3g) {
    __shared__ __align__(16) float sW1t[64 * 64];
    __shared__ __align__(16) float sW2t[64 * 64];
    __shared__ float sw0[64], sb0[64], sb1[64], sb2[64], sw3[64];
    __shared__ float sb3;

    const int s   = blockIdx.y;
    const int tid = threadIdx.x;

    // Load + transpose weights into smem (once per CTA; STS conflicts are
    // 32-way on the transpose but total cost ~1k cyc vs ~18k cyc of compute).
    const float* w1 = W1g + s * 4096;
    const float* w2 = W2g + s * 4096;
#pragma unroll
    for (int i = tid; i < 4096; i += 256) {
        int v = i >> 6, w = i & 63;
        sW1t[w * 64 + v] = w1[i];
        sW2t[w * 64 + v] = w2[i];
    }
    if (tid < 64) {
        sw0[tid] = W0g[s * 64 + tid];
        sb0[tid] = B0g[s * 64 + tid];
        sb1[tid] = B1g[s * 64 + tid];
        sb2[tid] = B2g[s * 64 + tid];
        sw3[tid] = W3g[s * 64 + tid];
    }
    if (tid == 0) sb3 = B3g[s];
    __syncthreads();

    const int n = blockIdx.x * 256 + tid;
    const float x = X[n];

    // Layer 0: h[w] = tanh(W0[s,w,0]*x + b0[s,w])
    float h[WID];
#pragma unroll
    for (int w = 0; w < 64; w++) h[w] = tanh_fast(fmaf(sw0[w], x, sb0[w]));

    // Two hidden layers (FFMA2-bound)
    layer64(sW1t, sb1, h);
    layer64(sW2t, sb2, h);

    // Output layer: u = W3[s,0,:] . h + b3[s]  (4 partial sums for ILP)
    float u0 = sb3, u1 = 0.f, u2 = 0.f, u3 = 0.f;
#pragma unroll
    for (int w = 0; w < 64; w += 4) {
        u0 = fmaf(sw3[w + 0], h[w + 0], u0);
        u1 = fmaf(sw3[w + 1], h[w + 1], u1);
        u2 = fmaf(sw3[w + 2], h[w + 2], u2);
        u3 = fmaf(sw3[w + 3], h[w + 3], u3);
    }
    g_u[s * NPTS + n] = (u0 + u1) + (u2 + u3);
}

// ---------------------------------------------------------------------------
// Kernel 2: Gaussian partition-of-unity reduction + hard-BC ansatz.
// out[n] = tanh(5x) * sum_s(raw_s*u_s) / sum_s(raw_s)
// raw_s = exp(-0.5*((x - s/63)/ (1.5/64))^2). 64 exps/point — trivial.
// ---------------------------------------------------------------------------
__global__ __launch_bounds__(256)
void fbpinn_reduce_kernel(const float* __restrict__ X, float* __restrict__ out) {
    const int n = blockIdx.x * 256 + threadIdx.x;
    const float x = X[n];
    const float inv_sigma = 64.0f / 1.5f;
    float num = 0.0f, den = 0.0f;
#pragma unroll
    for (int s = 0; s < 64; s++) {
        float t = (x - (float)s * (1.0f / 63.0f)) * inv_sigma;
        float r = __expf(-0.5f * t * t);
        num = fmaf(r, g_u[s * NPTS + n], num);
        den += r;
    }
    out[n] = tanh_fast(5.0f * x) * (num / den);
}

// ---------------------------------------------------------------------------
// Entry point. Inputs (metadata order): x, W0, b0, W1, b1, W2, b2, W3, b3.
// Output: float32 [65536]. Graph-capturable: two plain kernel launches.
// ---------------------------------------------------------------------------
extern "C" void kernel_launch(void* const* d_in, const int* in_sizes, int n_in,
                              void* d_out, int out_size) {
    const float* X  = (const float*)d_in[0];
    const float* W0 = (const float*)d_in[1];
    const float* B0 = (const float*)d_in[2];
    const float* W1 = (const float*)d_in[3];
    const float* B1 = (const float*)d_in[4];
    const float* W2 = (const float*)d_in[5];
    const float* B2 = (const float*)d_in[6];
    const float* W3 = (const float*)d_in[7];
    const float* B3 = (const float*)d_in[8];
    float* out = (float*)d_out;

    dim3 grid(NPTS / 256, NSUB);
    fbpinn_mlp_kernel<<<grid, 256>>>(X, W0, B0, W1, B1, W2, B2, W3, B3);
    fbpinn_reduce_kernel<<<NPTS / 256, 256>>>(X, out);
}